// round 15
// baseline (speedup 1.0000x reference)
#include <cuda_runtime.h>
#include <cuda_fp16.h>

#define TPB 64            // 2 independent warps per CTA
#define IMG_H 512
#define IMG_W 512
#define BAND 52           // emit rows per band (10*52 = 520 >= 512)
#define N_ITERS 60        // 52 emit + 8 halo, multiple of 12 (ring period)
#define N_BLOCKS 2560     // grid (256 x 10)

__device__ double g_acc = 0.0;
__device__ unsigned int g_count = 0;

struct h2x2 { __half2 a, b; };   // 4 h-values packed, 8 bytes

// Load row (guarded).
#define LOAD_ROW(L_, A_, B_, H_)                                              \
    do {                                                                      \
        const int L = (L_);                                                   \
        if ((unsigned)L < (unsigned)rowEnd) {                                 \
            const float4* p = base4 + (size_t)L * (IMG_W / 4) + iA;           \
            A_ = __ldg(p); B_ = __ldg(p + 1);                                 \
            H_ = haloAct ? __ldg(p + hOff) : make_float4(0.f, 0.f, 0.f, 0.f); \
        } else {                                                              \
            A_ = B_ = H_ = make_float4(0.f, 0.f, 0.f, 0.f);                   \
        }                                                                     \
    } while (0)

// Process one row. h quantized to fp16 BEFORE the S add and the ring store,
// so the subtract 9 rows later cancels exactly.
// h-ring: depth 12, read slot (KS_+3)%12 (delay 9), write slot KS_%12.
// x-ring: depth 4, read-then-write slot KX_%4 (delay 4).
#define PROCESS_ROW(i_, KS_, KX_, cA_, cB_, cH_)                              \
    do {                                                                      \
        float4 vL, vR;                                                        \
        vL.x = __shfl_up_sync(0xffffffffu, cB_.x, 1);                         \
        vL.y = __shfl_up_sync(0xffffffffu, cB_.y, 1);                         \
        vL.z = __shfl_up_sync(0xffffffffu, cB_.z, 1);                         \
        vL.w = __shfl_up_sync(0xffffffffu, cB_.w, 1);                         \
        vR.x = __shfl_down_sync(0xffffffffu, cA_.x, 1);                       \
        vR.y = __shfl_down_sync(0xffffffffu, cA_.y, 1);                       \
        vR.z = __shfl_down_sync(0xffffffffu, cA_.z, 1);                       \
        vR.w = __shfl_down_sync(0xffffffffu, cA_.w, 1);                       \
        if (lane == 0)  vL = cH_;                                             \
        if (lane == 31) vR = cH_;                                             \
        float h0 = ((vL.x + vL.y) + (vL.z + vL.w))                            \
                 + ((cA_.x + cA_.y) + (cA_.z + cA_.w)) + cB_.x;               \
        float h1 = h0 - vL.x + cB_.y;                                         \
        float h2 = h1 - vL.y + cB_.z;                                         \
        float h3 = h2 - vL.z + cB_.w;                                         \
        float h4 = h3 - vL.w + vR.x;                                          \
        float h5 = h4 - cA_.x + vR.y;                                         \
        float h6 = h5 - cA_.y + vR.z;                                         \
        float h7 = h6 - cA_.z + vR.w;                                         \
        h2x2 qA, qB;                                                          \
        qA.a = __floats2half2_rn(h0, h1);                                     \
        qA.b = __floats2half2_rn(h2, h3);                                     \
        qB.a = __floats2half2_rn(h4, h5);                                     \
        qB.b = __floats2half2_rn(h6, h7);                                     \
        const float2 qa01 = __half22float2(qA.a);                             \
        const float2 qa23 = __half22float2(qA.b);                             \
        const float2 qb01 = __half22float2(qB.a);                             \
        const float2 qb23 = __half22float2(qB.b);                             \
        const h2x2 oA = ringA[((KS_) + 3) % 12][tid];                         \
        const h2x2 oB = ringB[((KS_) + 3) % 12][tid];                         \
        const float2 oa01 = __half22float2(oA.a);                             \
        const float2 oa23 = __half22float2(oA.b);                             \
        const float2 ob01 = __half22float2(oB.a);                             \
        const float2 ob23 = __half22float2(oB.b);                             \
        Sa.x += qa01.x - oa01.x;  Sa.y += qa01.y - oa01.y;                    \
        Sa.z += qa23.x - oa23.x;  Sa.w += qa23.y - oa23.y;                    \
        Sb.x += qb01.x - ob01.x;  Sb.y += qb01.y - ob01.y;                    \
        Sb.z += qb23.x - ob23.x;  Sb.w += qb23.y - ob23.y;                    \
        ringA[(KS_) % 12][tid] = qA;                                          \
        ringB[(KS_) % 12][tid] = qB;                                          \
        const float4 xa = xrA[(KX_) % 4];   /* read: x from row i-4 */        \
        const float4 xb = xrB[(KX_) % 4];                                     \
        xrA[(KX_) % 4] = cA_;               /* then overwrite with row i */   \
        xrB[(KX_) % 4] = cB_;                                                 \
        const int r = rowStart - 8 + (i_);                                    \
        if ((i_) >= 8 && r < IMG_H) {                                         \
            acc_sq = fmaf(xa.x, xa.x, acc_sq);                                \
            acc_sq = fmaf(xa.y, xa.y, acc_sq);                                \
            acc_sq = fmaf(xa.z, xa.z, acc_sq);                                \
            acc_sq = fmaf(xa.w, xa.w, acc_sq);                                \
            acc_sq = fmaf(xb.x, xb.x, acc_sq);                                \
            acc_sq = fmaf(xb.y, xb.y, acc_sq);                                \
            acc_sq = fmaf(xb.z, xb.z, acc_sq);                                \
            acc_sq = fmaf(xb.w, xb.w, acc_sq);                                \
            acc_xs = fmaf(xa.x, Sa.x, acc_xs);                                \
            acc_xs = fmaf(xa.y, Sa.y, acc_xs);                                \
            acc_xs = fmaf(xa.z, Sa.z, acc_xs);                                \
            acc_xs = fmaf(xa.w, Sa.w, acc_xs);                                \
            acc_xs = fmaf(xb.x, Sb.x, acc_xs);                                \
            acc_xs = fmaf(xb.y, Sb.y, acc_xs);                                \
            acc_xs = fmaf(xb.z, Sb.z, acc_xs);                                \
            acc_xs = fmaf(xb.w, Sb.w, acc_xs);                                \
            const float4 xs = (colhalf == 0) ? xa : xb;                       \
            acc_w = fmaf(w4.x * xs.x, xs.x, acc_w);                           \
            acc_w = fmaf(w4.y * xs.y, xs.y, acc_w);                           \
            acc_w = fmaf(w4.z * xs.z, xs.z, acc_w);                           \
            acc_w = fmaf(w4.w * xs.w, xs.w, acc_w);                           \
            const bool rowB = (r < 4) | (r > IMG_H - 5);                      \
            if (rowB) {                                                       \
                float rowsq = 0.f, roww = 0.f;                                \
                rowsq += xa.x * xa.x + xa.y * xa.y + xa.z * xa.z + xa.w * xa.w; \
                rowsq += xb.x * xb.x + xb.y * xb.y + xb.z * xb.z + xb.w * xb.w; \
                roww = fmaf(w4.x * xs.x, xs.x, roww);                         \
                roww = fmaf(w4.y * xs.y, xs.y, roww);                         \
                roww = fmaf(w4.z * xs.z, xs.z, roww);                         \
                roww = fmaf(w4.w * xs.w, xs.w, roww);                         \
                const float cnth = (float)(min(r, 4) + min(IMG_H - 1 - r, 4) + 1); \
                acc_c = fmaf(9.0f - cnth, fmaf(9.0f, rowsq, -roww), acc_c);   \
            }                                                                 \
        }                                                                     \
    } while (0)

__global__ void __launch_bounds__(TPB, 10) sc_main(const float* __restrict__ img,
                                                   float* __restrict__ out) {
    const int tid  = threadIdx.x;
    const int lane = tid & 31;
    const int wid  = tid >> 5;
    const int plane   = blockIdx.x;
    const int region  = blockIdx.y * 2 + wid;   // 0..19
    const int colhalf = region & 1;
    const int vband   = region >> 1;            // 0..9
    const int rowStart = vband * BAND;
    const int rowEnd   = min(IMG_H, rowStart + BAND + 4);  // last h-row + 1

    const float4* base4 = (const float4*)img + (size_t)plane * (IMG_H * (IMG_W / 4));
    const int iA = colhalf * 64 + 2 * lane;

    const bool haloAct = (lane == 0 && colhalf == 1) || (lane == 31 && colhalf == 0);
    const int  hOff    = (lane == 0) ? -1 : 2;

    const int cbase = colhalf * 256 + 8 * lane;
    const int cj = (colhalf == 0) ? cbase : cbase + 4;
    float4 w4;
    w4.x = (float)(max(4 - (cj + 0), 0) + max((cj + 0) - 507, 0));
    w4.y = (float)(max(4 - (cj + 1), 0) + max((cj + 1) - 507, 0));
    w4.z = (float)(max(4 - (cj + 2), 0) + max((cj + 2) - 507, 0));
    w4.w = (float)(max(4 - (cj + 3), 0) + max((cj + 3) - 507, 0));

    // fp16-compressed h ring, depth 12 (period matches unroll 12)
    __shared__ h2x2 ringA[12][TPB];
    __shared__ h2x2 ringB[12][TPB];
    const h2x2 zero16 = { __floats2half2_rn(0.f, 0.f), __floats2half2_rn(0.f, 0.f) };
#pragma unroll
    for (int i = 0; i < 12; i++) {
        ringA[i][tid] = zero16;
        ringB[i][tid] = zero16;
    }

    float4 xrA[4], xrB[4];      // x ring, depth 4, read-then-write (delay 4)
#pragma unroll
    for (int i = 0; i < 4; i++) {
        xrA[i] = make_float4(0.f, 0.f, 0.f, 0.f);
        xrB[i] = make_float4(0.f, 0.f, 0.f, 0.f);
    }
    float4 Sa = make_float4(0.f, 0.f, 0.f, 0.f);
    float4 Sb = make_float4(0.f, 0.f, 0.f, 0.f);
    float acc_sq = 0.f, acc_xs = 0.f, acc_w = 0.f, acc_c = 0.f;

    // single-row pipeline: row i resident, row i+1 loaded at iteration top
    float4 cA, cB, cH;
    LOAD_ROW(rowStart - 4, cA, cB, cH);

    for (int it = 0; it < N_ITERS / 12; ++it) {
#pragma unroll
        for (int kk = 0; kk < 12; ++kk) {
            const int i = it * 12 + kk;

            float4 nA, nB, nH;
            LOAD_ROW(rowStart - 3 + i, nA, nB, nH);

            PROCESS_ROW(i, kk, kk, cA, cB, cH);

            cA = nA; cB = nB; cH = nH;
        }
    }

    float acc = fmaf(162.0f, acc_sq, fmaf(-2.0f, acc_xs, -fmaf(9.0f, acc_w, acc_c)));

    // warp reduce -> CTA reduce -> one atomic per CTA; last CTA finalizes
#pragma unroll
    for (int off = 16; off; off >>= 1) acc += __shfl_down_sync(0xffffffffu, acc, off);
    __shared__ float wsum[2];
    if (lane == 0) wsum[wid] = acc;
    __syncthreads();
    if (tid == 0) {
        atomicAdd(&g_acc, (double)(wsum[0] + wsum[1]));
        __threadfence();
        unsigned int t = atomicAdd(&g_count, 1u);
        if (t == N_BLOCKS - 1) {
            out[0] = (float)(g_acc * 0.125);   // mean over batch of 8
            g_acc = 0.0;
            g_count = 0u;
        }
    }
}

extern "C" void kernel_launch(void* const* d_in, const int* in_sizes, int n_in,
                              void* d_out, int out_size) {
    const float* img = (const float*)d_in[0];
    dim3 grid(256, 10);         // 2560 CTAs = N_BLOCKS
    sc_main<<<grid, TPB>>>(img, (float*)d_out);
}

// round 16
// speedup vs baseline: 1.1086x; 1.1086x over previous
#include <cuda_runtime.h>
#include <cuda_fp16.h>

#define TPB 64            // 2 independent warps per CTA
#define IMG_H 512
#define IMG_W 512
#define BAND 64           // emit rows per band (8*64 = 512, exact)
#define N_ITERS 72        // 64 emit + 8 halo, multiple of 12 (ring period)
#define N_BLOCKS 2048     // grid (256 x 8)

__device__ double g_acc = 0.0;
__device__ unsigned int g_count = 0;

struct h2x2 { __half2 a, b; };   // 4 h-values packed, 8 bytes

// Load row (guarded): batched at iteration top for MLP.
#define LOAD_ROW(L_, A_, B_, H_)                                              \
    do {                                                                      \
        const int L = (L_);                                                   \
        if ((unsigned)L < (unsigned)rowEnd) {                                 \
            const float4* p = base4 + (size_t)L * (IMG_W / 4) + iA;           \
            A_ = __ldg(p); B_ = __ldg(p + 1);                                 \
            H_ = haloAct ? __ldg(p + hOff) : make_float4(0.f, 0.f, 0.f, 0.f); \
        } else {                                                              \
            A_ = B_ = H_ = make_float4(0.f, 0.f, 0.f, 0.f);                   \
        }                                                                     \
    } while (0)

// L2 prefetch of one row (clamped): no register destination, no scoreboard.
// One line-granular prefetch covers this thread's A and B float4s.
#define PREFETCH_ROW(L_)                                                      \
    do {                                                                      \
        const int Lp = min((L_), rowEnd - 1);                                 \
        const float4* pp = base4 + (size_t)Lp * (IMG_W / 4) + iA;             \
        asm volatile("prefetch.global.L2 [%0];" :: "l"(pp));                  \
    } while (0)

// Process one row. h quantized to fp16 BEFORE the S add and the ring store,
// so the subtract 9 rows later cancels exactly.
// h-ring: depth 12, read slot (KS_+3)%12 (delay 9), write slot KS_%12.
// x-ring: depth 4, read-then-write slot KX_%4 (delay 4).
#define PROCESS_ROW(i_, KS_, KX_, cA_, cB_, cH_)                              \
    do {                                                                      \
        float4 vL, vR;                                                        \
        vL.x = __shfl_up_sync(0xffffffffu, cB_.x, 1);                         \
        vL.y = __shfl_up_sync(0xffffffffu, cB_.y, 1);                         \
        vL.z = __shfl_up_sync(0xffffffffu, cB_.z, 1);                         \
        vL.w = __shfl_up_sync(0xffffffffu, cB_.w, 1);                         \
        vR.x = __shfl_down_sync(0xffffffffu, cA_.x, 1);                       \
        vR.y = __shfl_down_sync(0xffffffffu, cA_.y, 1);                       \
        vR.z = __shfl_down_sync(0xffffffffu, cA_.z, 1);                       \
        vR.w = __shfl_down_sync(0xffffffffu, cA_.w, 1);                       \
        if (lane == 0)  vL = cH_;                                             \
        if (lane == 31) vR = cH_;                                             \
        float h0 = ((vL.x + vL.y) + (vL.z + vL.w))                            \
                 + ((cA_.x + cA_.y) + (cA_.z + cA_.w)) + cB_.x;               \
        float h1 = h0 - vL.x + cB_.y;                                         \
        float h2 = h1 - vL.y + cB_.z;                                         \
        float h3 = h2 - vL.z + cB_.w;                                         \
        float h4 = h3 - vL.w + vR.x;                                          \
        float h5 = h4 - cA_.x + vR.y;                                         \
        float h6 = h5 - cA_.y + vR.z;                                         \
        float h7 = h6 - cA_.z + vR.w;                                         \
        h2x2 qA, qB;                                                          \
        qA.a = __floats2half2_rn(h0, h1);                                     \
        qA.b = __floats2half2_rn(h2, h3);                                     \
        qB.a = __floats2half2_rn(h4, h5);                                     \
        qB.b = __floats2half2_rn(h6, h7);                                     \
        const float2 qa01 = __half22float2(qA.a);                             \
        const float2 qa23 = __half22float2(qA.b);                             \
        const float2 qb01 = __half22float2(qB.a);                             \
        const float2 qb23 = __half22float2(qB.b);                             \
        const h2x2 oA = ringA[((KS_) + 3) % 12][tid];                         \
        const h2x2 oB = ringB[((KS_) + 3) % 12][tid];                         \
        const float2 oa01 = __half22float2(oA.a);                             \
        const float2 oa23 = __half22float2(oA.b);                             \
        const float2 ob01 = __half22float2(oB.a);                             \
        const float2 ob23 = __half22float2(oB.b);                             \
        Sa.x += qa01.x - oa01.x;  Sa.y += qa01.y - oa01.y;                    \
        Sa.z += qa23.x - oa23.x;  Sa.w += qa23.y - oa23.y;                    \
        Sb.x += qb01.x - ob01.x;  Sb.y += qb01.y - ob01.y;                    \
        Sb.z += qb23.x - ob23.x;  Sb.w += qb23.y - ob23.y;                    \
        ringA[(KS_) % 12][tid] = qA;                                          \
        ringB[(KS_) % 12][tid] = qB;                                          \
        const float4 xa = xrA[(KX_) % 4];   /* read: x from row i-4 */        \
        const float4 xb = xrB[(KX_) % 4];                                     \
        xrA[(KX_) % 4] = cA_;               /* then overwrite with row i */   \
        xrB[(KX_) % 4] = cB_;                                                 \
        if ((i_) >= 8) {                                                      \
            acc_sq = fmaf(xa.x, xa.x, acc_sq);                                \
            acc_sq = fmaf(xa.y, xa.y, acc_sq);                                \
            acc_sq = fmaf(xa.z, xa.z, acc_sq);                                \
            acc_sq = fmaf(xa.w, xa.w, acc_sq);                                \
            acc_sq = fmaf(xb.x, xb.x, acc_sq);                                \
            acc_sq = fmaf(xb.y, xb.y, acc_sq);                                \
            acc_sq = fmaf(xb.z, xb.z, acc_sq);                                \
            acc_sq = fmaf(xb.w, xb.w, acc_sq);                                \
            acc_xs = fmaf(xa.x, Sa.x, acc_xs);                                \
            acc_xs = fmaf(xa.y, Sa.y, acc_xs);                                \
            acc_xs = fmaf(xa.z, Sa.z, acc_xs);                                \
            acc_xs = fmaf(xa.w, Sa.w, acc_xs);                                \
            acc_xs = fmaf(xb.x, Sb.x, acc_xs);                                \
            acc_xs = fmaf(xb.y, Sb.y, acc_xs);                                \
            acc_xs = fmaf(xb.z, Sb.z, acc_xs);                                \
            acc_xs = fmaf(xb.w, Sb.w, acc_xs);                                \
            const float4 xs = (colhalf == 0) ? xa : xb;                       \
            acc_w = fmaf(w4.x * xs.x, xs.x, acc_w);                           \
            acc_w = fmaf(w4.y * xs.y, xs.y, acc_w);                           \
            acc_w = fmaf(w4.z * xs.z, xs.z, acc_w);                           \
            acc_w = fmaf(w4.w * xs.w, xs.w, acc_w);                           \
            const int r = rowStart - 8 + (i_);                                \
            const bool rowB = (r < 4) | (r > IMG_H - 5);                      \
            if (rowB) {                                                       \
                float rowsq = 0.f, roww = 0.f;                                \
                rowsq += xa.x * xa.x + xa.y * xa.y + xa.z * xa.z + xa.w * xa.w; \
                rowsq += xb.x * xb.x + xb.y * xb.y + xb.z * xb.z + xb.w * xb.w; \
                roww = fmaf(w4.x * xs.x, xs.x, roww);                         \
                roww = fmaf(w4.y * xs.y, xs.y, roww);                         \
                roww = fmaf(w4.z * xs.z, xs.z, roww);                         \
                roww = fmaf(w4.w * xs.w, xs.w, roww);                         \
                const float cnth = (float)(min(r, 4) + min(IMG_H - 1 - r, 4) + 1); \
                acc_c = fmaf(9.0f - cnth, fmaf(9.0f, rowsq, -roww), acc_c);   \
            }                                                                 \
        }                                                                     \
    } while (0)

__global__ void __launch_bounds__(TPB, 8) sc_main(const float* __restrict__ img,
                                                  float* __restrict__ out) {
    const int tid  = threadIdx.x;
    const int lane = tid & 31;
    const int wid  = tid >> 5;
    const int plane   = blockIdx.x;
    const int region  = blockIdx.y * 2 + wid;   // 0..15
    const int colhalf = region & 1;
    const int vband   = region >> 1;            // 0..7
    const int rowStart = vband * BAND;
    const int rowEnd   = min(IMG_H, rowStart + BAND + 4);  // last h-row + 1

    const float4* base4 = (const float4*)img + (size_t)plane * (IMG_H * (IMG_W / 4));
    const int iA = colhalf * 64 + 2 * lane;

    const bool haloAct = (lane == 0 && colhalf == 1) || (lane == 31 && colhalf == 0);
    const int  hOff    = (lane == 0) ? -1 : 2;

    const int cbase = colhalf * 256 + 8 * lane;
    const int cj = (colhalf == 0) ? cbase : cbase + 4;
    float4 w4;
    w4.x = (float)(max(4 - (cj + 0), 0) + max((cj + 0) - 507, 0));
    w4.y = (float)(max(4 - (cj + 1), 0) + max((cj + 1) - 507, 0));
    w4.z = (float)(max(4 - (cj + 2), 0) + max((cj + 2) - 507, 0));
    w4.w = (float)(max(4 - (cj + 3), 0) + max((cj + 3) - 507, 0));

    // fp16-compressed h ring, depth 12 (period matches unroll 12)
    __shared__ h2x2 ringA[12][TPB];
    __shared__ h2x2 ringB[12][TPB];
    const h2x2 zero16 = { __floats2half2_rn(0.f, 0.f), __floats2half2_rn(0.f, 0.f) };
#pragma unroll
    for (int i = 0; i < 12; i++) {
        ringA[i][tid] = zero16;
        ringB[i][tid] = zero16;
    }

    float4 xrA[4], xrB[4];      // x ring, depth 4, read-then-write (delay 4)
#pragma unroll
    for (int i = 0; i < 4; i++) {
        xrA[i] = make_float4(0.f, 0.f, 0.f, 0.f);
        xrB[i] = make_float4(0.f, 0.f, 0.f, 0.f);
    }
    float4 Sa = make_float4(0.f, 0.f, 0.f, 0.f);
    float4 Sb = make_float4(0.f, 0.f, 0.f, 0.f);
    float acc_sq = 0.f, acc_xs = 0.f, acc_w = 0.f, acc_c = 0.f;

    // pipeline: rows i and i+1 resident, rows i+2/i+3 loaded at iteration top
    float4 c0A, c0B, c0H, c1A, c1B, c1H;
    LOAD_ROW(rowStart - 4, c0A, c0B, c0H);
    LOAD_ROW(rowStart - 3, c1A, c1B, c1H);
    PREFETCH_ROW(rowStart - 2);
    PREFETCH_ROW(rowStart - 1);
    PREFETCH_ROW(rowStart);
    PREFETCH_ROW(rowStart + 1);

    for (int it = 0; it < N_ITERS / 12; ++it) {
#pragma unroll
        for (int kk = 0; kk < 6; ++kk) {
            const int i0 = it * 12 + 2 * kk;

            // batched prefetch of the next row pair (front-batched LDGs),
            // plus L2 prefetch 6 rows ahead of consumption (no reg cost)
            float4 n0A, n0B, n0H, n1A, n1B, n1H;
            LOAD_ROW(rowStart - 2 + i0, n0A, n0B, n0H);
            LOAD_ROW(rowStart - 1 + i0, n1A, n1B, n1H);
            PREFETCH_ROW(rowStart + 2 + i0);
            PREFETCH_ROW(rowStart + 3 + i0);

            PROCESS_ROW(i0,     2 * kk,     2 * kk,     c0A, c0B, c0H);
            PROCESS_ROW(i0 + 1, 2 * kk + 1, 2 * kk + 1, c1A, c1B, c1H);

            c0A = n0A; c0B = n0B; c0H = n0H;
            c1A = n1A; c1B = n1B; c1H = n1H;
        }
    }

    float acc = fmaf(162.0f, acc_sq, fmaf(-2.0f, acc_xs, -fmaf(9.0f, acc_w, acc_c)));

    // warp reduce -> CTA reduce -> one atomic per CTA; last CTA finalizes
#pragma unroll
    for (int off = 16; off; off >>= 1) acc += __shfl_down_sync(0xffffffffu, acc, off);
    __shared__ float wsum[2];
    if (lane == 0) wsum[wid] = acc;
    __syncthreads();
    if (tid == 0) {
        atomicAdd(&g_acc, (double)(wsum[0] + wsum[1]));
        __threadfence();
        unsigned int t = atomicAdd(&g_count, 1u);
        if (t == N_BLOCKS - 1) {
            out[0] = (float)(g_acc * 0.125);   // mean over batch of 8
            g_acc = 0.0;
            g_count = 0u;
        }
    }
}

extern "C" void kernel_launch(void* const* d_in, const int* in_sizes, int n_in,
                              void* d_out, int out_size) {
    const float* img = (const float*)d_in[0];
    dim3 grid(256, 8);          // 2048 CTAs = N_BLOCKS
    sc_main<<<grid, TPB>>>(img, (float*)d_out);
}